// round 12
// baseline (speedup 1.0000x reference)
#include <cuda_runtime.h>
#include <cstdint>

#define NNODES 100000
#define NEDGES 1000000
#define ETOT   (NEDGES + NNODES)
#define NGRAPH 512
#define NB     148
#define NT     1024
#define CSRB   32             // blocks dedicated to CSR build
#define CHUNK2 3136           // ceil(NNODES/CSRB) rounded to x4

// shared-memory layout offsets (bytes)
#define SOFF_W    66560
#define SOFF_AS   132096
#define SOFF_AD   132608
#define SOFF_SC   133120
#define SOFF_SH   133632
#define SOFF_B    134144
#define SOFF_ST   134656
#define SMEM_TOT  135680

// ---------------- scratch (device globals) ----------------------------------
__device__ __align__(16) float g_h  [(size_t)NNODES * 128];
__device__ __align__(16) float g_h2 [(size_t)NNODES * 128];
__device__ float g_as [(size_t)NNODES * 8];
__device__ float g_ad [(size_t)NNODES * 8];
__device__ int   g_deg   [NNODES];
__device__ int   g_cursor[NNODES];
__device__ int   g_incl  [NNODES];
__device__ int   g_rowptr[NNODES + 1];
__device__ int   g_csr   [ETOT];
__device__ int   g_bsum  [256];
__device__ float g_bnacc [5 * 256];
__device__ float g_pool  [NGRAPH * 64];
__device__ float g_cnt   [NGRAPH];
__device__ int   g_work  [16];

__device__ int           g_barcnt = 0;
__device__ volatile int  g_barflag = 0;
__device__ int           g_gcnt = 0;
__device__ volatile int  g_gflag = 0;
__device__ int           g_done = 0;

// ---------------- f32x2 packed math helpers ----------------------------------
__device__ __forceinline__ unsigned long long pack2(float v) {
    unsigned long long r; unsigned u = __float_as_uint(v);
    asm("mov.b64 %0, {%1, %1};" : "=l"(r) : "r"(u));
    return r;
}
__device__ __forceinline__ void fma2(unsigned long long& d, unsigned long long a,
                                     unsigned long long b) {
    asm("fma.rn.f32x2 %0, %1, %2, %0;" : "+l"(d) : "l"(a), "l"(b));
}
__device__ __forceinline__ void unpack2(unsigned long long v, float& lo, float& hi) {
    unsigned a, b;
    asm("mov.b64 {%0, %1}, %2;" : "=r"(a), "=r"(b) : "l"(v));
    lo = __uint_as_float(a); hi = __uint_as_float(b);
}

// ---------------- barriers ----------------------------------------------------
__device__ __forceinline__ void gbar(int& sense) {
    __syncthreads();
    sense += 1;
    if (threadIdx.x == 0) {
        __threadfence();
        int v = atomicAdd(&g_barcnt, 1);
        if (v == NB - 1) {
            g_barcnt = 0;
            __threadfence();
            g_barflag = sense;
        } else {
            while (g_barflag < sense) { __nanosleep(64); }
        }
        __threadfence();
    }
    __syncthreads();
}

__device__ __forceinline__ void gbar_csr(int& gs) {
    __syncthreads();
    gs += 1;
    if (threadIdx.x == 0) {
        __threadfence();
        int v = atomicAdd(&g_gcnt, 1);
        if (v == CSRB - 1) {
            g_gcnt = 0;
            __threadfence();
            g_gflag = gs;
        } else {
            while (g_gflag < gs) { __nanosleep(64); }
        }
        __threadfence();
    }
    __syncthreads();
}

// ---------------- CSR-group phases (blocks 0..CSRB-1) ------------------------
__device__ __forceinline__ void zero_phase() {
    int gid = blockIdx.x * NT + threadIdx.x;
    if (gid < NNODES)      g_deg[gid] = 0;
    if (gid < 5 * 256)     g_bnacc[gid] = 0.f;
    if (gid < NGRAPH * 64) g_pool[gid] = 0.f;
    if (gid < NGRAPH)      g_cnt[gid] = 0.f;
    if (gid < 16)          g_work[gid] = 0;
}

__device__ __forceinline__ void hist32(const int* __restrict__ ei) {
    for (int t = blockIdx.x * NT + threadIdx.x; t < ETOT; t += CSRB * NT) {
        int d = (t < NEDGES) ? ei[NEDGES + t] : (t - NEDGES);
        atomicAdd(&g_deg[d], 1);
    }
}

__device__ __forceinline__ void scan32(int* ssm) {
    int j = threadIdx.x;
    int base = blockIdx.x * CHUNK2 + j * 4;
    int a0 = 0, a1 = 0, a2 = 0, a3 = 0;
    bool act = (j * 4) < CHUNK2;
    if (act) {
        a0 = (base + 0 < NNODES) ? g_deg[base + 0] : 0;
        a1 = (base + 1 < NNODES) ? g_deg[base + 1] : 0;
        a2 = (base + 2 < NNODES) ? g_deg[base + 2] : 0;
        a3 = (base + 3 < NNODES) ? g_deg[base + 3] : 0;
    }
    int p0 = a0, p1 = p0 + a1, p2 = p1 + a2, p3 = p2 + a3;
    ssm[j] = p3; __syncthreads();
    for (int off = 1; off < NT; off <<= 1) {
        int t = (j >= off) ? ssm[j - off] : 0;
        __syncthreads();
        ssm[j] += t;
        __syncthreads();
    }
    int excl = ssm[j] - p3;
    if (act) {
        if (base + 0 < NNODES) g_incl[base + 0] = excl + p0;
        if (base + 1 < NNODES) g_incl[base + 1] = excl + p1;
        if (base + 2 < NNODES) g_incl[base + 2] = excl + p2;
        if (base + 3 < NNODES) g_incl[base + 3] = excl + p3;
    }
    if (j == NT - 1) g_bsum[blockIdx.x] = ssm[NT - 1];
}

__device__ __forceinline__ void scanfix32(int* ssm) {
    int j = threadIdx.x;
    if (j < CSRB) ssm[j] = g_bsum[j];
    __syncthreads();
    int off = 0;
    for (int k = 0; k < (int)blockIdx.x; k++) off += ssm[k];
    int base = blockIdx.x * CHUNK2 + j * 4;
    if ((j * 4) < CHUNK2) {
#pragma unroll
        for (int i = 0; i < 4; i++) {
            int g = base + i;
            if (g < NNODES) {
                g_rowptr[g + 1] = g_incl[g] + off;
                g_cursor[g] = 0;
            }
        }
    }
    if (blockIdx.x == 0 && j == 0) g_rowptr[0] = 0;
}

__device__ __forceinline__ void scatter32(const int* __restrict__ ei) {
    for (int t = blockIdx.x * NT + threadIdx.x; t < ETOT; t += CSRB * NT) {
        int s, d;
        if (t < NEDGES) { s = ei[t]; d = ei[NEDGES + t]; }
        else            { s = t - NEDGES; d = t - NEDGES; }
        int pos = atomicAdd(&g_cursor[d], 1);
        g_csr[g_rowptr[d] + pos] = s;
    }
}

// ---------------- wide GEMM: column-pair f32x2, conflict-free W reads --------
template<int K, int CO, int CPT, bool XFORM, int H>
__device__ void gemm_wide(const float* __restrict__ X, const float* __restrict__ W,
                          float* __restrict__ Y,
                          const float* __restrict__ asv, const float* __restrict__ adv,
                          const float* __restrict__ gamma, const float* __restrict__ beta,
                          int slot_in, int n, int workid, char* sdyn)
{
    constexpr int BM  = 128;
    constexpr int BMP = 130;
    constexpr int ch  = CO / H;
    constexpr int LPH = ch / CPT;
    constexpr int NP  = CPT / 2;     // f32x2 col-pairs per thread
    float* sXs = (float*)sdyn;
    float* sW  = (float*)(sdyn + SOFF_W);
    float* sAs = (float*)(sdyn + SOFF_AS);
    float* sAd = (float*)(sdyn + SOFF_AD);
    float* sSc = (float*)(sdyn + SOFF_SC);
    float* sSh = (float*)(sdyn + SOFF_SH);
    __shared__ int s_tile;

    for (int idx = threadIdx.x; idx < K * CO / 4; idx += NT)
        ((float4*)sW)[idx] = ((const float4*)W)[idx];
    if (XFORM && threadIdx.x < K) {
        float invn = 1.f / (float)n;
        float mean = g_bnacc[slot_in * 256 + threadIdx.x] * invn;
        float var  = g_bnacc[slot_in * 256 + 128 + threadIdx.x] * invn - mean * mean;
        float rs   = rsqrtf(var + 1e-5f);
        float sc   = gamma[threadIdx.x] * rs;
        sSc[threadIdx.x] = sc;
        sSh[threadIdx.x] = beta[threadIdx.x] - sc * mean;
    }
    if (threadIdx.x < CO) {
        sAs[threadIdx.x] = asv[threadIdx.x];
        sAd[threadIdx.x] = adv[threadIdx.x];
    }
    if (threadIdx.x == 0) s_tile = atomicAdd(&g_work[workid], 1);
    __syncthreads();

    int warp = threadIdx.x >> 5, lane = threadIdx.x & 31;
    int c0 = lane * CPT;
    int r0l = warp * 4;
    int ntiles = (n + BM - 1) / BM;
    int tile = s_tile;

    while (tile < ntiles) {
        int row0 = tile * BM;
        for (int idx = threadIdx.x; idx < BM * K; idx += NT) {
            int r = idx / K, k = idx - r * K;
            int gr = row0 + r;
            float v = (gr < n) ? X[(size_t)gr * K + k] : 0.f;
            if (XFORM) v = fmaxf(v * sSc[k] + sSh[k], 0.f);
            sXs[k * BMP + r] = v;
        }
        __syncthreads();

        unsigned long long acc[4][NP];
#pragma unroll
        for (int i = 0; i < 4; i++)
#pragma unroll
            for (int p = 0; p < NP; p++) acc[i][p] = 0ull;

        if (c0 < CO) {
#pragma unroll 4
            for (int k = 0; k < K; k++) {
                const float* xr = &sXs[k * BMP + r0l];
                unsigned long long ap0 = pack2(xr[0]);
                unsigned long long ap1 = pack2(xr[1]);
                unsigned long long ap2 = pack2(xr[2]);
                unsigned long long ap3 = pack2(xr[3]);
                if (CPT == 4) {
                    float4 w4 = *(const float4*)&sW[k * CO + c0];   // LDS.128, no conflict
                    unsigned long long b01 = ((const unsigned long long*)&w4)[0];
                    unsigned long long b23 = ((const unsigned long long*)&w4)[1];
                    fma2(acc[0][0], ap0, b01); fma2(acc[0][NP - 1], ap0, b23);
                    fma2(acc[1][0], ap1, b01); fma2(acc[1][NP - 1], ap1, b23);
                    fma2(acc[2][0], ap2, b01); fma2(acc[2][NP - 1], ap2, b23);
                    fma2(acc[3][0], ap3, b01); fma2(acc[3][NP - 1], ap3, b23);
                } else {
                    float2 w2 = *(const float2*)&sW[k * CO + c0];   // LDS.64, no conflict
                    unsigned long long b01 = *(const unsigned long long*)&w2;
                    fma2(acc[0][0], ap0, b01);
                    fma2(acc[1][0], ap1, b01);
                    fma2(acc[2][0], ap2, b01);
                    fma2(acc[3][0], ap3, b01);
                }
            }
        }

        float o[4][CPT];
#pragma unroll
        for (int i = 0; i < 4; i++) {
            unpack2(acc[i][0], o[i][0], o[i][1]);
            if (CPT == 4) unpack2(acc[i][NP - 1], o[i][CPT - 2], o[i][CPT - 1]);
        }

        // fused alpha epilogue
#pragma unroll
        for (int i = 0; i < 4; i++) {
            float ps = 0.f, pd = 0.f;
            if (c0 < CO) {
#pragma unroll
                for (int u = 0; u < CPT; u++) {
                    ps += o[i][u] * sAs[c0 + u];
                    pd += o[i][u] * sAd[c0 + u];
                }
            }
            int g0 = (lane / LPH) * LPH;
            float ss = 0.f, sd = 0.f;
#pragma unroll
            for (int u = 0; u < LPH; u++) {
                ss += __shfl_sync(0xffffffffu, ps, g0 + u);
                sd += __shfl_sync(0xffffffffu, pd, g0 + u);
            }
            int r = row0 + r0l + i;
            if (c0 < CO && (lane % LPH) == 0 && r < n) {
                int hh = c0 / ch;
                g_as[(size_t)r * H + hh] = ss;
                g_ad[(size_t)r * H + hh] = sd;
            }
        }

        if (c0 < CO) {
#pragma unroll
            for (int i = 0; i < 4; i++) {
                int r = row0 + r0l + i;
                if (r < n) {
                    if (CPT == 4) {
                        float4 ov = make_float4(o[i][0], o[i][1],
                                                o[i][CPT > 2 ? 2 : 0],
                                                o[i][CPT > 3 ? 3 : 0]);
                        *(float4*)(Y + (size_t)r * CO + c0) = ov;
                    } else {
                        float2 ov = make_float2(o[i][0], o[i][1]);
                        *(float2*)(Y + (size_t)r * CO + c0) = ov;
                    }
                }
            }
        }
        __syncthreads();
        if (threadIdx.x == 0) s_tile = atomicAdd(&g_work[workid], 1);
        __syncthreads();
        tile = s_tile;
    }
}

// ---------------- skinny GEMM + fused output BN stats ------------------------
template<int K, int CO>
__device__ void gemm_skinny(const float* __restrict__ X, const float* __restrict__ W,
                            const float* __restrict__ bias, float* __restrict__ Y,
                            const float* __restrict__ gamma, const float* __restrict__ beta,
                            int slot_in, int slot_out, int n, int workid, char* sdyn)
{
    float* sW  = (float*)sdyn;
    float* sSc = (float*)(sdyn + SOFF_SC);
    float* sSh = (float*)(sdyn + SOFF_SH);
    float* sB  = (float*)(sdyn + SOFF_B);
    float* sStat = (float*)(sdyn + SOFF_ST);
    __shared__ int s_base;

    for (int idx = threadIdx.x; idx < K * CO; idx += NT) sW[idx] = W[idx];
    if (threadIdx.x < K) {
        float invn = 1.f / (float)n;
        float mean = g_bnacc[slot_in * 256 + threadIdx.x] * invn;
        float var  = g_bnacc[slot_in * 256 + 128 + threadIdx.x] * invn - mean * mean;
        float rs   = rsqrtf(var + 1e-5f);
        float sc   = gamma[threadIdx.x] * rs;
        sSc[threadIdx.x] = sc;
        sSh[threadIdx.x] = beta[threadIdx.x] - sc * mean;
    }
    if (threadIdx.x < CO) sB[threadIdx.x] = bias[threadIdx.x];
    if (threadIdx.x < 2 * CO) sStat[threadIdx.x] = 0.f;

    int lane = threadIdx.x & 31;
    for (;;) {
        __syncthreads();
        if (threadIdx.x == 0) s_base = atomicAdd(&g_work[workid], NT);
        __syncthreads();
        int base = s_base;
        if (base >= n) break;
        int row = base + threadIdx.x;

        float outv[CO];
#pragma unroll
        for (int c = 0; c < CO; c++) outv[c] = 0.f;

        if (row < n) {
            unsigned long long acc2[CO / 2];
#pragma unroll
            for (int c = 0; c < CO / 2; c++) acc2[c] = 0ull;
#pragma unroll 4
            for (int k4 = 0; k4 < K / 4; k4++) {
                float4 xv = *(const float4*)(X + (size_t)row * K + 4 * k4);
                xv.x = fmaxf(xv.x * sSc[4 * k4 + 0] + sSh[4 * k4 + 0], 0.f);
                xv.y = fmaxf(xv.y * sSc[4 * k4 + 1] + sSh[4 * k4 + 1], 0.f);
                xv.z = fmaxf(xv.z * sSc[4 * k4 + 2] + sSh[4 * k4 + 2], 0.f);
                xv.w = fmaxf(xv.w * sSc[4 * k4 + 3] + sSh[4 * k4 + 3], 0.f);
                unsigned long long xp0 = pack2(xv.x), xp1 = pack2(xv.y);
                unsigned long long xp2 = pack2(xv.z), xp3 = pack2(xv.w);
                const float* w0 = sW + (4 * k4) * CO;
#pragma unroll
                for (int c2 = 0; c2 < CO / 2; c2++) {
                    fma2(acc2[c2], xp0, *(const unsigned long long*)&w0[2 * c2]);
                    fma2(acc2[c2], xp1, *(const unsigned long long*)&w0[CO + 2 * c2]);
                    fma2(acc2[c2], xp2, *(const unsigned long long*)&w0[2 * CO + 2 * c2]);
                    fma2(acc2[c2], xp3, *(const unsigned long long*)&w0[3 * CO + 2 * c2]);
                }
            }
#pragma unroll
            for (int c2 = 0; c2 < CO / 2; c2++)
                unpack2(acc2[c2], outv[2 * c2], outv[2 * c2 + 1]);
#pragma unroll
            for (int c = 0; c < CO; c++) outv[c] += sB[c];
#pragma unroll
            for (int c4 = 0; c4 < CO / 4; c4++) {
                float4 ov = make_float4(outv[4 * c4], outv[4 * c4 + 1],
                                        outv[4 * c4 + 2], outv[4 * c4 + 3]);
                *(float4*)(Y + (size_t)row * CO + 4 * c4) = ov;
            }
        }
#pragma unroll
        for (int c = 0; c < CO; c++) {
            float v = (row < n) ? outv[c] : 0.f;
            float v2 = v * v;
#pragma unroll
            for (int off = 16; off; off >>= 1) {
                v  += __shfl_xor_sync(0xffffffffu, v, off);
                v2 += __shfl_xor_sync(0xffffffffu, v2, off);
            }
            if (lane == 0) {
                atomicAdd(&sStat[c], v);
                atomicAdd(&sStat[CO + c], v2);
            }
        }
    }
    __syncthreads();
    if (threadIdx.x < CO) {
        atomicAdd(&g_bnacc[slot_out * 256 + threadIdx.x], sStat[threadIdx.x]);
        atomicAdd(&g_bnacc[slot_out * 256 + 128 + threadIdx.x], sStat[CO + threadIdx.x]);
    }
}

// ---------------- GAT aggregation: cp.async smem-ring pipelined gather -------
// Per-warp steal of 16 contiguous dsts => contiguous CSR edge window.
// Depth-6 LDGSTS ring (640B/edge: 512B feature + 128B logit), zero register
// cost for in-flight data.
template<int C, int H>
__device__ void agg_phase(const float* __restrict__ h, const float* __restrict__ bias,
                          float* __restrict__ out, int n, int slot, int workid,
                          char* sdyn)
{
    constexpr int NL = C / 4;
    constexpr int ch = C / H;
    constexpr int P  = 6;
    constexpr int SLOT_B = 640;
    constexpr int GRAIN = 16;

    float* sStat = (float*)(sdyn + SOFF_ST);
    if (threadIdx.x < 2 * C) sStat[threadIdx.x] = 0.f;
    __syncthreads();

    int warp = threadIdx.x >> 5;
    int lane = threadIdx.x & 31;
    bool act = lane < NL;
    int hd = act ? (4 * lane) / ch : 0;

    unsigned sbase;
    asm("{ .reg .u64 t; cvta.to.shared.u64 t, %1; cvt.u32.u64 %0, t; }"
        : "=r"(sbase) : "l"(sdyn));
    unsigned fA = sbase + warp * (P * SLOT_B) + lane * 16;
    unsigned aA = sbase + warp * (P * SLOT_B) + 512 + lane * 4;

    float4 bv = make_float4(0.f, 0.f, 0.f, 0.f);
    if (act) bv = *(const float4*)(bias + 4 * lane);
    float4 sum = make_float4(0.f, 0.f, 0.f, 0.f);
    float4 sq  = make_float4(0.f, 0.f, 0.f, 0.f);

    for (;;) {
        int base = 0;
        if (lane == 0) base = atomicAdd(&g_work[workid], GRAIN);
        base = __shfl_sync(0xffffffffu, base, 0);
        if (base >= n) {
            asm volatile("cp.async.wait_group 0;");
            break;
        }
        int dend = (base + GRAIN < n) ? base + GRAIN : n;
        int B = g_rowptr[base];
        int E = g_rowptr[dend];
        int tot = E - B;

        // prologue: prefetch edges 0..P-1 (one commit group each)
        int sCur = g_csr[B];
#pragma unroll
        for (int j = 0; j < P; j++) {
            if (j < tot && act) {
                unsigned fo = fA + j * SLOT_B;
                unsigned ao = aA + j * SLOT_B;
                const float* gf = h + (size_t)sCur * C + 4 * lane;
                const float* ga = g_as + (size_t)sCur * H + hd;
                asm volatile("cp.async.ca.shared.global [%0], [%1], 16;"
                             :: "r"(fo), "l"(gf));
                asm volatile("cp.async.ca.shared.global [%0], [%1], 4;"
                             :: "r"(ao), "l"(ga));
            }
            asm volatile("cp.async.commit_group;");
            if (B + j + 1 < E) sCur = g_csr[B + j + 1];
        }
        // sCur now holds csr[B+P] (if it exists)

        int slotC = 0;
        int i = 0;                                   // consume stream index
        float adl = act ? g_ad[(size_t)base * H + hd] : 0.f;
        for (int d = base; d < dend; d++) {
            float adlN = (act && d + 1 < dend) ? g_ad[(size_t)(d + 1) * H + hd] : 0.f;
            int cnt = g_rowptr[d + 1] - g_rowptr[d];
            float den = 0.f;
            float4 acc = make_float4(0.f, 0.f, 0.f, 0.f);
            for (int e = 0; e < cnt; e++) {
                asm volatile("cp.async.wait_group %0;" :: "n"(P - 1));
                float asv = 0.f;
                float4 f = make_float4(0.f, 0.f, 0.f, 0.f);
                unsigned fo = fA + slotC * SLOT_B;
                unsigned ao = aA + slotC * SLOT_B;
                if (act) {
                    asm volatile("ld.shared.v4.f32 {%0,%1,%2,%3}, [%4];"
                                 : "=f"(f.x), "=f"(f.y), "=f"(f.z), "=f"(f.w)
                                 : "r"(fo));
                    asm volatile("ld.shared.f32 %0, [%1];" : "=f"(asv) : "r"(ao));
                }
                // compute first: scoreboard on f/asv guarantees the LDS reads
                // finished before the slot is re-targeted below.
                float v = asv + adl;
                v = (v > 0.f) ? v : 0.2f * v;
                float w = __expf(v);
                den += w;
                acc.x += w * f.x; acc.y += w * f.y;
                acc.z += w * f.z; acc.w += w * f.w;
                // prefetch edge i+P into the freed slot
                int pi = i + P;
                if (pi < tot && act) {
                    const float* gf = h + (size_t)sCur * C + 4 * lane;
                    const float* ga = g_as + (size_t)sCur * H + hd;
                    asm volatile("cp.async.ca.shared.global [%0], [%1], 16;"
                                 :: "r"(fo), "l"(gf));
                    asm volatile("cp.async.ca.shared.global [%0], [%1], 4;"
                                 :: "r"(ao), "l"(ga));
                }
                asm volatile("cp.async.commit_group;");
                if (B + pi + 1 < E) sCur = g_csr[B + pi + 1];
                slotC = (slotC + 1 == P) ? 0 : slotC + 1;
                i++;
            }
            if (act) {
                float inv = 1.f / (den + 1e-16f);
                float4 o;
                o.x = acc.x * inv + bv.x;
                o.y = acc.y * inv + bv.y;
                o.z = acc.z * inv + bv.z;
                o.w = acc.w * inv + bv.w;
                *(float4*)(out + (size_t)d * C + 4 * lane) = o;
                sum.x += o.x; sum.y += o.y; sum.z += o.z; sum.w += o.w;
                sq.x += o.x * o.x; sq.y += o.y * o.y;
                sq.z += o.z * o.z; sq.w += o.w * o.w;
            }
            adl = adlN;
        }
        // drain before the next window reuses the ring
        asm volatile("cp.async.wait_group 0;");
    }
    if (act) {
        atomicAdd(&sStat[4 * lane + 0], sum.x);
        atomicAdd(&sStat[4 * lane + 1], sum.y);
        atomicAdd(&sStat[4 * lane + 2], sum.z);
        atomicAdd(&sStat[4 * lane + 3], sum.w);
        atomicAdd(&sStat[C + 4 * lane + 0], sq.x);
        atomicAdd(&sStat[C + 4 * lane + 1], sq.y);
        atomicAdd(&sStat[C + 4 * lane + 2], sq.z);
        atomicAdd(&sStat[C + 4 * lane + 3], sq.w);
    }
    __syncthreads();
    if (threadIdx.x < C) {
        atomicAdd(&g_bnacc[slot * 256 + threadIdx.x], sStat[threadIdx.x]);
        atomicAdd(&g_bnacc[slot * 256 + 128 + threadIdx.x], sStat[C + threadIdx.x]);
    }
}

// ---------------- pooling + classifier ---------------------------------------
__device__ void pool_phase(const float* __restrict__ h, const int* __restrict__ batch,
                           int n, const float* __restrict__ gamma,
                           const float* __restrict__ beta, float* sSc, float* sSh)
{
    if (threadIdx.x < 64) {
        float invn = 1.f / (float)n;
        float mean = g_bnacc[4 * 256 + threadIdx.x] * invn;
        float var  = g_bnacc[4 * 256 + 128 + threadIdx.x] * invn - mean * mean;
        float rs   = rsqrtf(var + 1e-5f);
        float sc   = gamma[threadIdx.x] * rs;
        sSc[threadIdx.x] = sc;
        sSh[threadIdx.x] = beta[threadIdx.x] - sc * mean;
    }
    __syncthreads();
    int t = blockIdx.x * NT + threadIdx.x;
    int c = t & 63;
    int rt = t >> 6;
    int T = (NB * NT) >> 6;
    int chunk = (n + T - 1) / T;
    int n0 = rt * chunk;
    int n1 = (n0 + chunk < n) ? (n0 + chunk) : n;
    int gcur = -1; float acc = 0.f; float cnt = 0.f;
    float sc = sSc[c], sh = sSh[c];
    for (int nn = n0; nn < n1; nn++) {
        int g = batch[nn];
        float v = fmaxf(h[(size_t)nn * 64 + c] * sc + sh, 0.f);
        if (g != gcur) {
            if (gcur >= 0) {
                atomicAdd(&g_pool[gcur * 64 + c], acc);
                if (c == 0) atomicAdd(&g_cnt[gcur], cnt);
            }
            gcur = g; acc = v; cnt = 1.f;
        } else { acc += v; cnt += 1.f; }
    }
    if (gcur >= 0) {
        atomicAdd(&g_pool[gcur * 64 + c], acc);
        if (c == 0) atomicAdd(&g_cnt[gcur], cnt);
    }
}

__device__ void classify_phase(const float* __restrict__ Wo, const float* __restrict__ bo,
                               float* __restrict__ out)
{
    int t = blockIdx.x * NT + threadIdx.x;
    if (t < NGRAPH * 10) {
        int g = t / 10, cls = t - g * 10;
        float inv = 1.f / fmaxf(g_cnt[g], 1.f);
        float s = bo[cls];
#pragma unroll 16
        for (int k = 0; k < 64; k++)
            s += g_pool[g * 64 + k] * inv * Wo[k * 10 + cls];
        out[t] = s;
    }
}

// ---------------- megakernel -------------------------------------------------
__global__ void __launch_bounds__(NT, 1) megakernel(
    const float* __restrict__ x, const int* __restrict__ ei, const int* __restrict__ batch,
    const float* W1, const float* as1, const float* ad1, const float* b1,
    const float* g1, const float* be1,
    const float* Wl1, const float* bl1, const float* gl1, const float* bel1,
    const float* W2, const float* as2, const float* ad2, const float* b2,
    const float* g2, const float* be2,
    const float* Wl2, const float* bl2, const float* gl2, const float* bel2,
    const float* W3, const float* as3, const float* ad3, const float* b3,
    const float* g3, const float* be3,
    const float* Wo, const float* bo, float* out)
{
    extern __shared__ char sdyn[];
    const int n = NNODES;
    int sense = 0;
    int gs = 0;

    zero_phase();                                                   gbar(sense);

    // CSR build (blocks 0..CSRB-1) overlapped with GEMM1+alpha; CSR blocks
    // JOIN the GEMM via the shared tile counter once scatter finishes.
    if (blockIdx.x < CSRB) {
        hist32(ei);        gbar_csr(gs);
        scan32((int*)sdyn); gbar_csr(gs);
        scanfix32((int*)sdyn); gbar_csr(gs);
        scatter32(ei);
        gemm_wide<128, 128, 4, false, 8>(x, W1, g_h, as1, ad1,
                                         nullptr, nullptr, 0, n, 0, sdyn);
    } else {
        gemm_wide<128, 128, 4, false, 8>(x, W1, g_h, as1, ad1,
                                         nullptr, nullptr, 0, n, 0, sdyn);
    }
                                                                    gbar(sense);
    agg_phase<128, 8>(g_h, b1, g_h2, n, 0, 1, sdyn);                gbar(sense);
    gemm_skinny<128, 16>(g_h2, Wl1, bl1, g_h, g1, be1, 0, 1, n, 2, sdyn);
                                                                    gbar(sense);
    gemm_wide<16, 96, 4, true, 4>(g_h, W2, g_h2, as2, ad2,
                                  gl1, bel1, 1, n, 3, sdyn);        gbar(sense);
    agg_phase<96, 4>(g_h2, b2, g_h, n, 2, 4, sdyn);                 gbar(sense);
    gemm_skinny<96, 24>(g_h, Wl2, bl2, g_h2, g2, be2, 2, 3, n, 5, sdyn);
                                                                    gbar(sense);
    gemm_wide<24, 64, 2, true, 2>(g_h2, W3, g_h, as3, ad3,
                                  gl2, bel2, 3, n, 6, sdyn);        gbar(sense);
    agg_phase<64, 2>(g_h, b3, g_h2, n, 4, 7, sdyn);                 gbar(sense);
    pool_phase(g_h2, batch, n, g3, be3, (float*)(sdyn + SOFF_SC),
               (float*)(sdyn + SOFF_SH));                           gbar(sense);
    classify_phase(Wo, bo, out);

    __syncthreads();
    if (threadIdx.x == 0) {
        __threadfence();
        if (atomicAdd(&g_done, 1) == NB - 1) {
            g_done = 0;
            g_barcnt = 0;
            g_barflag = 0;
            g_gcnt = 0;
            g_gflag = 0;
        }
    }
}

// ---------------- launch -----------------------------------------------------
extern "C" void kernel_launch(void* const* d_in, const int* in_sizes, int n_in,
                              void* d_out, int out_size) {
    static int configured = 0;
    if (!configured) {
        cudaFuncSetAttribute(megakernel, cudaFuncAttributeMaxDynamicSharedMemorySize,
                             SMEM_TOT);
        configured = 1;
    }
    megakernel<<<NB, NT, SMEM_TOT>>>(
        (const float*)d_in[0], (const int*)d_in[1], (const int*)d_in[2],
        (const float*)d_in[3],  (const float*)d_in[4],  (const float*)d_in[5],
        (const float*)d_in[6],  (const float*)d_in[7],  (const float*)d_in[8],
        (const float*)d_in[9],  (const float*)d_in[10], (const float*)d_in[11],
        (const float*)d_in[12],
        (const float*)d_in[13], (const float*)d_in[14], (const float*)d_in[15],
        (const float*)d_in[16], (const float*)d_in[17], (const float*)d_in[18],
        (const float*)d_in[19], (const float*)d_in[20], (const float*)d_in[21],
        (const float*)d_in[22],
        (const float*)d_in[23], (const float*)d_in[24], (const float*)d_in[25],
        (const float*)d_in[26], (const float*)d_in[27], (const float*)d_in[28],
        (const float*)d_in[29], (const float*)d_in[30],
        (float*)d_out);
}

// round 16
// speedup vs baseline: 1.2222x; 1.2222x over previous
#include <cuda_runtime.h>
#include <cstdint>

#define NNODES 100000
#define NEDGES 1000000
#define ETOT   (NEDGES + NNODES)
#define NGRAPH 512
#define NB     148
#define NT     1024
#define CSRB   32             // blocks dedicated to CSR build
#define CHUNK2 3136           // ceil(NNODES/CSRB) rounded to x4

// shared-memory layout offsets (bytes)
#define SOFF_W    66560
#define SOFF_AS   132096
#define SOFF_AD   132608
#define SOFF_SC   133120
#define SOFF_SH   133632
#define SOFF_B    134144
#define SOFF_ST   134656
#define SMEM_TOT  135680

// ---------------- scratch (device globals) ----------------------------------
__device__ __align__(16) float g_h  [(size_t)NNODES * 128];
__device__ __align__(16) float g_h2 [(size_t)NNODES * 128];
__device__ float g_as [(size_t)NNODES * 8];
__device__ float g_ad [(size_t)NNODES * 8];
__device__ int   g_deg   [NNODES];
__device__ int   g_cursor[NNODES];
__device__ int   g_incl  [NNODES];
__device__ int   g_rowptr[NNODES + 1];
__device__ int   g_csr   [ETOT];
__device__ int   g_bsum  [256];
__device__ float g_bnacc [5 * 256];
__device__ float g_pool  [NGRAPH * 64];
__device__ float g_cnt   [NGRAPH];
__device__ int   g_work  [16];

__device__ int           g_barcnt = 0;
__device__ volatile int  g_barflag = 0;
__device__ int           g_gcnt = 0;
__device__ volatile int  g_gflag = 0;
__device__ int           g_done = 0;

// ---------------- f32x2 packed math helpers ----------------------------------
__device__ __forceinline__ unsigned long long pack2(float v) {
    unsigned long long r; unsigned u = __float_as_uint(v);
    asm("mov.b64 %0, {%1, %1};" : "=l"(r) : "r"(u));
    return r;
}
__device__ __forceinline__ void fma2(unsigned long long& d, unsigned long long a,
                                     unsigned long long b) {
    asm("fma.rn.f32x2 %0, %1, %2, %0;" : "+l"(d) : "l"(a), "l"(b));
}
__device__ __forceinline__ void unpack2(unsigned long long v, float& lo, float& hi) {
    unsigned a, b;
    asm("mov.b64 {%0, %1}, %2;" : "=r"(a), "=r"(b) : "l"(v));
    lo = __uint_as_float(a); hi = __uint_as_float(b);
}

// ---------------- barriers ----------------------------------------------------
__device__ __forceinline__ void gbar(int& sense) {
    __syncthreads();
    sense += 1;
    if (threadIdx.x == 0) {
        __threadfence();
        int v = atomicAdd(&g_barcnt, 1);
        if (v == NB - 1) {
            g_barcnt = 0;
            __threadfence();
            g_barflag = sense;
        } else {
            while (g_barflag < sense) { __nanosleep(64); }
        }
        __threadfence();
    }
    __syncthreads();
}

__device__ __forceinline__ void gbar_csr(int& gs) {
    __syncthreads();
    gs += 1;
    if (threadIdx.x == 0) {
        __threadfence();
        int v = atomicAdd(&g_gcnt, 1);
        if (v == CSRB - 1) {
            g_gcnt = 0;
            __threadfence();
            g_gflag = gs;
        } else {
            while (g_gflag < gs) { __nanosleep(64); }
        }
        __threadfence();
    }
    __syncthreads();
}

// ---------------- CSR-group phases (blocks 0..CSRB-1) ------------------------
__device__ __forceinline__ void zero_phase() {
    int gid = blockIdx.x * NT + threadIdx.x;
    if (gid < NNODES)      g_deg[gid] = 0;
    if (gid < 5 * 256)     g_bnacc[gid] = 0.f;
    if (gid < NGRAPH * 64) g_pool[gid] = 0.f;
    if (gid < NGRAPH)      g_cnt[gid] = 0.f;
    if (gid < 16)          g_work[gid] = 0;
}

__device__ __forceinline__ void hist32(const int* __restrict__ ei) {
    for (int t = blockIdx.x * NT + threadIdx.x; t < ETOT; t += CSRB * NT) {
        int d = (t < NEDGES) ? ei[NEDGES + t] : (t - NEDGES);
        atomicAdd(&g_deg[d], 1);
    }
}

__device__ __forceinline__ void scan32(int* ssm) {
    int j = threadIdx.x;
    int base = blockIdx.x * CHUNK2 + j * 4;
    int a0 = 0, a1 = 0, a2 = 0, a3 = 0;
    bool act = (j * 4) < CHUNK2;
    if (act) {
        a0 = (base + 0 < NNODES) ? g_deg[base + 0] : 0;
        a1 = (base + 1 < NNODES) ? g_deg[base + 1] : 0;
        a2 = (base + 2 < NNODES) ? g_deg[base + 2] : 0;
        a3 = (base + 3 < NNODES) ? g_deg[base + 3] : 0;
    }
    int p0 = a0, p1 = p0 + a1, p2 = p1 + a2, p3 = p2 + a3;
    ssm[j] = p3; __syncthreads();
    for (int off = 1; off < NT; off <<= 1) {
        int t = (j >= off) ? ssm[j - off] : 0;
        __syncthreads();
        ssm[j] += t;
        __syncthreads();
    }
    int excl = ssm[j] - p3;
    if (act) {
        if (base + 0 < NNODES) g_incl[base + 0] = excl + p0;
        if (base + 1 < NNODES) g_incl[base + 1] = excl + p1;
        if (base + 2 < NNODES) g_incl[base + 2] = excl + p2;
        if (base + 3 < NNODES) g_incl[base + 3] = excl + p3;
    }
    if (j == NT - 1) g_bsum[blockIdx.x] = ssm[NT - 1];
}

__device__ __forceinline__ void scanfix32(int* ssm) {
    int j = threadIdx.x;
    if (j < CSRB) ssm[j] = g_bsum[j];
    __syncthreads();
    int off = 0;
    for (int k = 0; k < (int)blockIdx.x; k++) off += ssm[k];
    int base = blockIdx.x * CHUNK2 + j * 4;
    if ((j * 4) < CHUNK2) {
#pragma unroll
        for (int i = 0; i < 4; i++) {
            int g = base + i;
            if (g < NNODES) {
                g_rowptr[g + 1] = g_incl[g] + off;
                g_cursor[g] = 0;
            }
        }
    }
    if (blockIdx.x == 0 && j == 0) g_rowptr[0] = 0;
}

__device__ __forceinline__ void scatter32(const int* __restrict__ ei) {
    for (int t = blockIdx.x * NT + threadIdx.x; t < ETOT; t += CSRB * NT) {
        int s, d;
        if (t < NEDGES) { s = ei[t]; d = ei[NEDGES + t]; }
        else            { s = t - NEDGES; d = t - NEDGES; }
        int pos = atomicAdd(&g_cursor[d], 1);
        g_csr[g_rowptr[d] + pos] = s;
    }
}

// ---------------- wide GEMM: column-pair f32x2, conflict-free W reads --------
template<int K, int CO, int CPT, bool XFORM, int H>
__device__ void gemm_wide(const float* __restrict__ X, const float* __restrict__ W,
                          float* __restrict__ Y,
                          const float* __restrict__ asv, const float* __restrict__ adv,
                          const float* __restrict__ gamma, const float* __restrict__ beta,
                          int slot_in, int n, int workid, char* sdyn)
{
    constexpr int BM  = 128;
    constexpr int BMP = 130;
    constexpr int ch  = CO / H;
    constexpr int LPH = ch / CPT;
    constexpr int NP  = CPT / 2;     // f32x2 col-pairs per thread
    float* sXs = (float*)sdyn;
    float* sW  = (float*)(sdyn + SOFF_W);
    float* sAs = (float*)(sdyn + SOFF_AS);
    float* sAd = (float*)(sdyn + SOFF_AD);
    float* sSc = (float*)(sdyn + SOFF_SC);
    float* sSh = (float*)(sdyn + SOFF_SH);
    __shared__ int s_tile;

    for (int idx = threadIdx.x; idx < K * CO / 4; idx += NT)
        ((float4*)sW)[idx] = ((const float4*)W)[idx];
    if (XFORM && threadIdx.x < K) {
        float invn = 1.f / (float)n;
        float mean = g_bnacc[slot_in * 256 + threadIdx.x] * invn;
        float var  = g_bnacc[slot_in * 256 + 128 + threadIdx.x] * invn - mean * mean;
        float rs   = rsqrtf(var + 1e-5f);
        float sc   = gamma[threadIdx.x] * rs;
        sSc[threadIdx.x] = sc;
        sSh[threadIdx.x] = beta[threadIdx.x] - sc * mean;
    }
    if (threadIdx.x < CO) {
        sAs[threadIdx.x] = asv[threadIdx.x];
        sAd[threadIdx.x] = adv[threadIdx.x];
    }
    if (threadIdx.x == 0) s_tile = atomicAdd(&g_work[workid], 1);
    __syncthreads();

    int warp = threadIdx.x >> 5, lane = threadIdx.x & 31;
    int c0 = lane * CPT;
    int r0l = warp * 4;
    int ntiles = (n + BM - 1) / BM;
    int tile = s_tile;

    while (tile < ntiles) {
        int row0 = tile * BM;
        for (int idx = threadIdx.x; idx < BM * K; idx += NT) {
            int r = idx / K, k = idx - r * K;
            int gr = row0 + r;
            float v = (gr < n) ? X[(size_t)gr * K + k] : 0.f;
            if (XFORM) v = fmaxf(v * sSc[k] + sSh[k], 0.f);
            sXs[k * BMP + r] = v;
        }
        __syncthreads();

        unsigned long long acc[4][NP];
#pragma unroll
        for (int i = 0; i < 4; i++)
#pragma unroll
            for (int p = 0; p < NP; p++) acc[i][p] = 0ull;

        if (c0 < CO) {
#pragma unroll 4
            for (int k = 0; k < K; k++) {
                const float* xr = &sXs[k * BMP + r0l];
                unsigned long long ap0 = pack2(xr[0]);
                unsigned long long ap1 = pack2(xr[1]);
                unsigned long long ap2 = pack2(xr[2]);
                unsigned long long ap3 = pack2(xr[3]);
                if (CPT == 4) {
                    float4 w4 = *(const float4*)&sW[k * CO + c0];   // LDS.128, no conflict
                    unsigned long long b01 = ((const unsigned long long*)&w4)[0];
                    unsigned long long b23 = ((const unsigned long long*)&w4)[1];
                    fma2(acc[0][0], ap0, b01); fma2(acc[0][NP - 1], ap0, b23);
                    fma2(acc[1][0], ap1, b01); fma2(acc[1][NP - 1], ap1, b23);
                    fma2(acc[2][0], ap2, b01); fma2(acc[2][NP - 1], ap2, b23);
                    fma2(acc[3][0], ap3, b01); fma2(acc[3][NP - 1], ap3, b23);
                } else {
                    float2 w2 = *(const float2*)&sW[k * CO + c0];   // LDS.64, no conflict
                    unsigned long long b01 = *(const unsigned long long*)&w2;
                    fma2(acc[0][0], ap0, b01);
                    fma2(acc[1][0], ap1, b01);
                    fma2(acc[2][0], ap2, b01);
                    fma2(acc[3][0], ap3, b01);
                }
            }
        }

        float o[4][CPT];
#pragma unroll
        for (int i = 0; i < 4; i++) {
            unpack2(acc[i][0], o[i][0], o[i][1]);
            if (CPT == 4) unpack2(acc[i][NP - 1], o[i][CPT - 2], o[i][CPT - 1]);
        }

        // fused alpha epilogue
#pragma unroll
        for (int i = 0; i < 4; i++) {
            float ps = 0.f, pd = 0.f;
            if (c0 < CO) {
#pragma unroll
                for (int u = 0; u < CPT; u++) {
                    ps += o[i][u] * sAs[c0 + u];
                    pd += o[i][u] * sAd[c0 + u];
                }
            }
            int g0 = (lane / LPH) * LPH;
            float ss = 0.f, sd = 0.f;
#pragma unroll
            for (int u = 0; u < LPH; u++) {
                ss += __shfl_sync(0xffffffffu, ps, g0 + u);
                sd += __shfl_sync(0xffffffffu, pd, g0 + u);
            }
            int r = row0 + r0l + i;
            if (c0 < CO && (lane % LPH) == 0 && r < n) {
                int hh = c0 / ch;
                g_as[(size_t)r * H + hh] = ss;
                g_ad[(size_t)r * H + hh] = sd;
            }
        }

        if (c0 < CO) {
#pragma unroll
            for (int i = 0; i < 4; i++) {
                int r = row0 + r0l + i;
                if (r < n) {
                    if (CPT == 4) {
                        float4 ov = make_float4(o[i][0], o[i][1],
                                                o[i][CPT > 2 ? 2 : 0],
                                                o[i][CPT > 3 ? 3 : 0]);
                        *(float4*)(Y + (size_t)r * CO + c0) = ov;
                    } else {
                        float2 ov = make_float2(o[i][0], o[i][1]);
                        *(float2*)(Y + (size_t)r * CO + c0) = ov;
                    }
                }
            }
        }
        __syncthreads();
        if (threadIdx.x == 0) s_tile = atomicAdd(&g_work[workid], 1);
        __syncthreads();
        tile = s_tile;
    }
}

// ---------------- skinny GEMM + fused output BN stats ------------------------
template<int K, int CO>
__device__ void gemm_skinny(const float* __restrict__ X, const float* __restrict__ W,
                            const float* __restrict__ bias, float* __restrict__ Y,
                            const float* __restrict__ gamma, const float* __restrict__ beta,
                            int slot_in, int slot_out, int n, int workid, char* sdyn)
{
    float* sW  = (float*)sdyn;
    float* sSc = (float*)(sdyn + SOFF_SC);
    float* sSh = (float*)(sdyn + SOFF_SH);
    float* sB  = (float*)(sdyn + SOFF_B);
    float* sStat = (float*)(sdyn + SOFF_ST);
    __shared__ int s_base;

    for (int idx = threadIdx.x; idx < K * CO; idx += NT) sW[idx] = W[idx];
    if (threadIdx.x < K) {
        float invn = 1.f / (float)n;
        float mean = g_bnacc[slot_in * 256 + threadIdx.x] * invn;
        float var  = g_bnacc[slot_in * 256 + 128 + threadIdx.x] * invn - mean * mean;
        float rs   = rsqrtf(var + 1e-5f);
        float sc   = gamma[threadIdx.x] * rs;
        sSc[threadIdx.x] = sc;
        sSh[threadIdx.x] = beta[threadIdx.x] - sc * mean;
    }
    if (threadIdx.x < CO) sB[threadIdx.x] = bias[threadIdx.x];
    if (threadIdx.x < 2 * CO) sStat[threadIdx.x] = 0.f;

    int lane = threadIdx.x & 31;
    for (;;) {
        __syncthreads();
        if (threadIdx.x == 0) s_base = atomicAdd(&g_work[workid], NT);
        __syncthreads();
        int base = s_base;
        if (base >= n) break;
        int row = base + threadIdx.x;

        float outv[CO];
#pragma unroll
        for (int c = 0; c < CO; c++) outv[c] = 0.f;

        if (row < n) {
            unsigned long long acc2[CO / 2];
#pragma unroll
            for (int c = 0; c < CO / 2; c++) acc2[c] = 0ull;
#pragma unroll 4
            for (int k4 = 0; k4 < K / 4; k4++) {
                float4 xv = *(const float4*)(X + (size_t)row * K + 4 * k4);
                xv.x = fmaxf(xv.x * sSc[4 * k4 + 0] + sSh[4 * k4 + 0], 0.f);
                xv.y = fmaxf(xv.y * sSc[4 * k4 + 1] + sSh[4 * k4 + 1], 0.f);
                xv.z = fmaxf(xv.z * sSc[4 * k4 + 2] + sSh[4 * k4 + 2], 0.f);
                xv.w = fmaxf(xv.w * sSc[4 * k4 + 3] + sSh[4 * k4 + 3], 0.f);
                unsigned long long xp0 = pack2(xv.x), xp1 = pack2(xv.y);
                unsigned long long xp2 = pack2(xv.z), xp3 = pack2(xv.w);
                const float* w0 = sW + (4 * k4) * CO;
#pragma unroll
                for (int c2 = 0; c2 < CO / 2; c2++) {
                    fma2(acc2[c2], xp0, *(const unsigned long long*)&w0[2 * c2]);
                    fma2(acc2[c2], xp1, *(const unsigned long long*)&w0[CO + 2 * c2]);
                    fma2(acc2[c2], xp2, *(const unsigned long long*)&w0[2 * CO + 2 * c2]);
                    fma2(acc2[c2], xp3, *(const unsigned long long*)&w0[3 * CO + 2 * c2]);
                }
            }
#pragma unroll
            for (int c2 = 0; c2 < CO / 2; c2++)
                unpack2(acc2[c2], outv[2 * c2], outv[2 * c2 + 1]);
#pragma unroll
            for (int c = 0; c < CO; c++) outv[c] += sB[c];
#pragma unroll
            for (int c4 = 0; c4 < CO / 4; c4++) {
                float4 ov = make_float4(outv[4 * c4], outv[4 * c4 + 1],
                                        outv[4 * c4 + 2], outv[4 * c4 + 3]);
                *(float4*)(Y + (size_t)row * CO + 4 * c4) = ov;
            }
        }
#pragma unroll
        for (int c = 0; c < CO; c++) {
            float v = (row < n) ? outv[c] : 0.f;
            float v2 = v * v;
#pragma unroll
            for (int off = 16; off; off >>= 1) {
                v  += __shfl_xor_sync(0xffffffffu, v, off);
                v2 += __shfl_xor_sync(0xffffffffu, v2, off);
            }
            if (lane == 0) {
                atomicAdd(&sStat[c], v);
                atomicAdd(&sStat[CO + c], v2);
            }
        }
    }
    __syncthreads();
    if (threadIdx.x < CO) {
        atomicAdd(&g_bnacc[slot_out * 256 + threadIdx.x], sStat[threadIdx.x]);
        atomicAdd(&g_bnacc[slot_out * 256 + 128 + threadIdx.x], sStat[CO + threadIdx.x]);
    }
}

// ---------------- GAT aggregation: shfl-free, per-warp steal (GRAIN 8) -------
template<int C, int H>
__device__ void agg_phase(const float* __restrict__ h, const float* __restrict__ bias,
                          float* __restrict__ out, int n, int slot, int workid,
                          char* sdyn)
{
    float* sStat = (float*)sdyn;
    if (threadIdx.x < 2 * C) sStat[threadIdx.x] = 0.f;
    __syncthreads();

    constexpr int NL = C / 4;
    constexpr int ch = C / H;
    constexpr int GRAIN = 8;
    int lane = threadIdx.x & 31;
    bool act = lane < NL;
    int hd = act ? (4 * lane) / ch : 0;
    float4 bv = make_float4(0.f, 0.f, 0.f, 0.f);
    if (act) bv = *(const float4*)(bias + 4 * lane);
    float4 sum = make_float4(0.f, 0.f, 0.f, 0.f);
    float4 sq  = make_float4(0.f, 0.f, 0.f, 0.f);

    for (;;) {
        int base = 0;
        if (lane == 0) base = atomicAdd(&g_work[workid], GRAIN);
        base = __shfl_sync(0xffffffffu, base, 0);
        if (base >= n) break;
        int dend = (base + GRAIN < n) ? base + GRAIN : n;
        for (int d = base; d < dend; d++) {
            float ad_l = act ? g_ad[(size_t)d * H + hd] : 0.f;
            int beg = g_rowptr[d], end = g_rowptr[d + 1];
            float denom = 0.f;
            float4 acc = make_float4(0.f, 0.f, 0.f, 0.f);

            int s0 = g_csr[beg];
            float as0 = act ? g_as[(size_t)s0 * H + hd] : 0.f;
            float4 f0 = make_float4(0.f, 0.f, 0.f, 0.f);
            if (act) f0 = *(const float4*)(h + (size_t)s0 * C + 4 * lane);

            for (int e = beg; e < end; e++) {
                float as1v = 0.f;
                float4 f1 = make_float4(0.f, 0.f, 0.f, 0.f);
                if (e + 1 < end) {
                    int s1 = g_csr[e + 1];
                    if (act) {
                        as1v = g_as[(size_t)s1 * H + hd];
                        f1 = *(const float4*)(h + (size_t)s1 * C + 4 * lane);
                    }
                }
                float v = as0 + ad_l;
                v = (v > 0.f) ? v : 0.2f * v;
                float wv = __expf(v);
                denom += wv;
                acc.x += wv * f0.x; acc.y += wv * f0.y;
                acc.z += wv * f0.z; acc.w += wv * f0.w;
                as0 = as1v; f0 = f1;
            }
            if (act) {
                float inv = 1.f / (denom + 1e-16f);
                float4 o;
                o.x = acc.x * inv + bv.x;
                o.y = acc.y * inv + bv.y;
                o.z = acc.z * inv + bv.z;
                o.w = acc.w * inv + bv.w;
                *(float4*)(out + (size_t)d * C + 4 * lane) = o;
                sum.x += o.x; sum.y += o.y; sum.z += o.z; sum.w += o.w;
                sq.x += o.x * o.x; sq.y += o.y * o.y;
                sq.z += o.z * o.z; sq.w += o.w * o.w;
            }
        }
    }
    if (act) {
        atomicAdd(&sStat[4 * lane + 0], sum.x);
        atomicAdd(&sStat[4 * lane + 1], sum.y);
        atomicAdd(&sStat[4 * lane + 2], sum.z);
        atomicAdd(&sStat[4 * lane + 3], sum.w);
        atomicAdd(&sStat[C + 4 * lane + 0], sq.x);
        atomicAdd(&sStat[C + 4 * lane + 1], sq.y);
        atomicAdd(&sStat[C + 4 * lane + 2], sq.z);
        atomicAdd(&sStat[C + 4 * lane + 3], sq.w);
    }
    __syncthreads();
    if (threadIdx.x < C) {
        atomicAdd(&g_bnacc[slot * 256 + threadIdx.x], sStat[threadIdx.x]);
        atomicAdd(&g_bnacc[slot * 256 + 128 + threadIdx.x], sStat[C + threadIdx.x]);
    }
}

// ---------------- pooling + classifier ---------------------------------------
__device__ void pool_phase(const float* __restrict__ h, const int* __restrict__ batch,
                           int n, const float* __restrict__ gamma,
                           const float* __restrict__ beta, float* sSc, float* sSh)
{
    if (threadIdx.x < 64) {
        float invn = 1.f / (float)n;
        float mean = g_bnacc[4 * 256 + threadIdx.x] * invn;
        float var  = g_bnacc[4 * 256 + 128 + threadIdx.x] * invn - mean * mean;
        float rs   = rsqrtf(var + 1e-5f);
        float sc   = gamma[threadIdx.x] * rs;
        sSc[threadIdx.x] = sc;
        sSh[threadIdx.x] = beta[threadIdx.x] - sc * mean;
    }
    __syncthreads();
    int t = blockIdx.x * NT + threadIdx.x;
    int c = t & 63;
    int rt = t >> 6;
    int T = (NB * NT) >> 6;
    int chunk = (n + T - 1) / T;
    int n0 = rt * chunk;
    int n1 = (n0 + chunk < n) ? (n0 + chunk) : n;
    int gcur = -1; float acc = 0.f; float cnt = 0.f;
    float sc = sSc[c], sh = sSh[c];
    for (int nn = n0; nn < n1; nn++) {
        int g = batch[nn];
        float v = fmaxf(h[(size_t)nn * 64 + c] * sc + sh, 0.f);
        if (g != gcur) {
            if (gcur >= 0) {
                atomicAdd(&g_pool[gcur * 64 + c], acc);
                if (c == 0) atomicAdd(&g_cnt[gcur], cnt);
            }
            gcur = g; acc = v; cnt = 1.f;
        } else { acc += v; cnt += 1.f; }
    }
    if (gcur >= 0) {
        atomicAdd(&g_pool[gcur * 64 + c], acc);
        if (c == 0) atomicAdd(&g_cnt[gcur], cnt);
    }
}

__device__ void classify_phase(const float* __restrict__ Wo, const float* __restrict__ bo,
                               float* __restrict__ out)
{
    int t = blockIdx.x * NT + threadIdx.x;
    if (t < NGRAPH * 10) {
        int g = t / 10, cls = t - g * 10;
        float inv = 1.f / fmaxf(g_cnt[g], 1.f);
        float s = bo[cls];
#pragma unroll 16
        for (int k = 0; k < 64; k++)
            s += g_pool[g * 64 + k] * inv * Wo[k * 10 + cls];
        out[t] = s;
    }
}

// ---------------- megakernel -------------------------------------------------
__global__ void __launch_bounds__(NT, 1) megakernel(
    const float* __restrict__ x, const int* __restrict__ ei, const int* __restrict__ batch,
    const float* W1, const float* as1, const float* ad1, const float* b1,
    const float* g1, const float* be1,
    const float* Wl1, const float* bl1, const float* gl1, const float* bel1,
    const float* W2, const float* as2, const float* ad2, const float* b2,
    const float* g2, const float* be2,
    const float* Wl2, const float* bl2, const float* gl2, const float* bel2,
    const float* W3, const float* as3, const float* ad3, const float* b3,
    const float* g3, const float* be3,
    const float* Wo, const float* bo, float* out)
{
    extern __shared__ char sdyn[];
    const int n = NNODES;
    int sense = 0;
    int gs = 0;

    zero_phase();                                                   gbar(sense);

    // CSR build (blocks 0..CSRB-1) overlapped with GEMM1+alpha; CSR blocks
    // JOIN the GEMM via the shared tile counter once scatter finishes.
    if (blockIdx.x < CSRB) {
        hist32(ei);        gbar_csr(gs);
        scan32((int*)sdyn); gbar_csr(gs);
        scanfix32((int*)sdyn); gbar_csr(gs);
        scatter32(ei);
        gemm_wide<128, 128, 4, false, 8>(x, W1, g_h, as1, ad1,
                                         nullptr, nullptr, 0, n, 0, sdyn);
    } else {
        gemm_wide<128, 128, 4, false, 8>(x, W1, g_h, as1, ad1,
                                         nullptr, nullptr, 0, n, 0, sdyn);
    }
                                                                    gbar(sense);
    agg_phase<128, 8>(g_h, b1, g_h2, n, 0, 1, sdyn);                gbar(sense);
    gemm_skinny<128, 16>(g_h2, Wl1, bl1, g_h, g1, be1, 0, 1, n, 2, sdyn);
                                                                    gbar(sense);
    gemm_wide<16, 96, 4, true, 4>(g_h, W2, g_h2, as2, ad2,
                                  gl1, bel1, 1, n, 3, sdyn);        gbar(sense);
    agg_phase<96, 4>(g_h2, b2, g_h, n, 2, 4, sdyn);                 gbar(sense);
    gemm_skinny<96, 24>(g_h, Wl2, bl2, g_h2, g2, be2, 2, 3, n, 5, sdyn);
                                                                    gbar(sense);
    gemm_wide<24, 64, 2, true, 2>(g_h2, W3, g_h, as3, ad3,
                                  gl2, bel2, 3, n, 6, sdyn);        gbar(sense);
    agg_phase<64, 2>(g_h, b3, g_h2, n, 4, 7, sdyn);                 gbar(sense);
    pool_phase(g_h2, batch, n, g3, be3, (float*)(sdyn + SOFF_SC),
               (float*)(sdyn + SOFF_SH));                           gbar(sense);
    classify_phase(Wo, bo, out);

    __syncthreads();
    if (threadIdx.x == 0) {
        __threadfence();
        if (atomicAdd(&g_done, 1) == NB - 1) {
            g_done = 0;
            g_barcnt = 0;
            g_barflag = 0;
            g_gcnt = 0;
            g_gflag = 0;
        }
    }
}

// ---------------- launch -----------------------------------------------------
extern "C" void kernel_launch(void* const* d_in, const int* in_sizes, int n_in,
                              void* d_out, int out_size) {
    static int configured = 0;
    if (!configured) {
        cudaFuncSetAttribute(megakernel, cudaFuncAttributeMaxDynamicSharedMemorySize,
                             SMEM_TOT);
        configured = 1;
    }
    megakernel<<<NB, NT, SMEM_TOT>>>(
        (const float*)d_in[0], (const int*)d_in[1], (const int*)d_in[2],
        (const float*)d_in[3],  (const float*)d_in[4],  (const float*)d_in[5],
        (const float*)d_in[6],  (const float*)d_in[7],  (const float*)d_in[8],
        (const float*)d_in[9],  (const float*)d_in[10], (const float*)d_in[11],
        (const float*)d_in[12],
        (const float*)d_in[13], (const float*)d_in[14], (const float*)d_in[15],
        (const float*)d_in[16], (const float*)d_in[17], (const float*)d_in[18],
        (const float*)d_in[19], (const float*)d_in[20], (const float*)d_in[21],
        (const float*)d_in[22],
        (const float*)d_in[23], (const float*)d_in[24], (const float*)d_in[25],
        (const float*)d_in[26], (const float*)d_in[27], (const float*)d_in[28],
        (const float*)d_in[29], (const float*)d_in[30],
        (float*)d_out);
}